// round 10
// baseline (speedup 1.0000x reference)
#include <cuda_runtime.h>
#include <cuda_fp16.h>
#include <cstdint>

#define PP 64
#define HH 256
#define EE 64
#define BB 32
#define SS 128
#define G4 1024
#define NL 2048
#define NCTA 128
#define NTHR 512

#define ALPHA_F 0.1f
#define CMIX_F  0.0140625f
#define TINY_F  1.17549435e-38f

// ---------------- device scratch ----------------
__device__ float g_xg[SS * BB * G4];          // x@Wih^T + biases, gate-permuted cols
__device__ float g_xdot[SS * BB];
__device__ float g_Wih[G4 * EE];              // gate-permuted
__device__ float g_bias[G4];
__device__ __half g_W16[2][G4 * HH];          // Whh gate-permuted fp16 splits, row-major
__device__ __half g_h16[2][2][NL * HH];       // [pingpong][split] h fp16 splits, row-major
__device__ float g_c[2][NL * HH];             // ping-pong c
__device__ int   g_perm[NL];
__device__ float g_p[NL];
__device__ float g_pobs[8][NL];
__device__ float g_pout[8][NL];
__device__ uint2 g_sub[SS];
__device__ unsigned int g_barc, g_barg;

// ---------------- mma.sync helper (baseline PTX, works on compute_103) ----------------
__device__ __forceinline__ void mma16816(float* d, uint32_t a0, uint32_t a1,
                                         uint32_t a2, uint32_t a3,
                                         uint32_t b0, uint32_t b1) {
  asm volatile(
    "mma.sync.aligned.m16n8k16.row.col.f32.f16.f16.f32 "
    "{%0,%1,%2,%3}, {%4,%5,%6,%7}, {%8,%9}, {%0,%1,%2,%3};"
    : "+f"(d[0]), "+f"(d[1]), "+f"(d[2]), "+f"(d[3])
    : "r"(a0), "r"(a1), "r"(a2), "r"(a3), "r"(b0), "r"(b1));
}

// ---------------- grid barrier (128 CTAs, all resident) ----------------
__device__ __forceinline__ void grid_sync() {
  __syncthreads();
  if (threadIdx.x == 0) {
    __threadfence();
    unsigned int gen = *(volatile unsigned int*)&g_barg;
    if (atomicAdd(&g_barc, 1u) == NCTA - 1u) {
      atomicExch(&g_barc, 0u);
      __threadfence();
      atomicAdd(&g_barg, 1u);
    } else {
      while (*(volatile unsigned int*)&g_barg == gen) { __nanosleep(32); }
    }
    __threadfence();
  }
  __syncthreads();
}

// ---------------- threefry / gumbel ----------------
__device__ __forceinline__ void tf2x32(uint32_t k0, uint32_t k1, uint32_t x0, uint32_t x1,
                                       uint32_t& o0, uint32_t& o1) {
  uint32_t ks2 = k0 ^ k1 ^ 0x1BD11BDAu;
  x0 += k0; x1 += k1;
#define TFR(r) { x0 += x1; x1 = (x1 << (r)) | (x1 >> (32 - (r))); x1 ^= x0; }
  TFR(13) TFR(15) TFR(26) TFR(6)   x0 += k1;  x1 += ks2 + 1u;
  TFR(17) TFR(29) TFR(16) TFR(24)  x0 += ks2; x1 += k0  + 2u;
  TFR(13) TFR(15) TFR(26) TFR(6)   x0 += k0;  x1 += k1  + 3u;
  TFR(17) TFR(29) TFR(16) TFR(24)  x0 += k1;  x1 += ks2 + 4u;
  TFR(13) TFR(15) TFR(26) TFR(6)   x0 += ks2; x1 += k0  + 5u;
#undef TFR
  o0 = x0; o1 = x1;
}
__device__ __forceinline__ float gumbel_from(uint32_t k0, uint32_t k1, uint32_t flat) {
  uint32_t o0, o1;
  tf2x32(k0, k1, 0u, flat, o0, o1);
  uint32_t bits = o0 ^ o1;
  float f = __uint_as_float((bits >> 9) | 0x3F800000u) - 1.0f;
  f = fmaxf(f, TINY_F);
  return -logf(-logf(f));
}
__device__ __forceinline__ float sigm(float x) { return 1.0f / (1.0f + expf(-x)); }
__device__ __forceinline__ float lrelu(float x) { return x >= 0.0f ? x : 0.01f * x; }

// ---------------- prologue kernels ----------------
__global__ void k_prep_keys() {
  if (threadIdx.x == 0 && blockIdx.x == 0) {
    uint32_t k0 = 0u, k1 = 42u;
    for (int t = 0; t < SS; t++) {
      uint32_t n0, n1, s0, s1;
      tf2x32(k0, k1, 0u, 0u, n0, n1);
      tf2x32(k0, k1, 0u, 1u, s0, s1);
      g_sub[t] = make_uint2(s0, s1);
      k0 = n0; k1 = n1;
    }
  }
}

__global__ void k_init(const float* __restrict__ h0, const float* __restrict__ c0) {
  int i = blockIdx.x * blockDim.x + threadIdx.x;
  if (i < NL * HH) {
    g_c[0][i] = c0[i];
    float v = h0[i];
    __half a1 = __float2half_rn(v);
    __half a2 = __float2half_rn(v - __half2float(a1));
    g_h16[0][0][i] = a1; g_h16[0][1][i] = a2;
  }
  if (i < NL) { g_p[i] = -4.158883083359672f; g_perm[i] = i; }
}

// gate-permute rows (n = 4u+g <- g*H+u), split Whh to fp16x2, pack Wih + bias
__global__ void k_permW(const float* __restrict__ Whh, const float* __restrict__ Wih,
                        const float* __restrict__ bih, const float* __restrict__ bhh) {
  int n = blockIdx.x;
  int u = n >> 2, g = n & 3;
  int src = g * HH + u;
  int k = threadIdx.x;
  float v = Whh[src * HH + k];
  __half b1 = __float2half_rn(v);
  __half b2 = __float2half_rn(v - __half2float(b1));
  g_W16[0][n * HH + k] = b1;
  g_W16[1][n * HH + k] = b2;
  if (k < EE) g_Wih[n * EE + k] = Wih[src * EE + k];
  if (k == 0) g_bias[n] = bih[src] + bhh[src];
}

// xg = obs-rows @ g_Wih^T + g_bias  (4096x1024, K=64)
__global__ void __launch_bounds__(256, 1) k_xg2(const float* __restrict__ obs) {
  __shared__ float As[EE][132];
  __shared__ float Bs[EE][132];
  int bn = blockIdx.x, bm = blockIdx.y, tid = threadIdx.x;
  for (int e = tid; e < 128 * 16; e += 256) {
    int row = e >> 4, c4 = (e & 15) * 4;
    int gr = bm * 128 + row;
    int t = gr >> 5, b = gr & 31;
    float4 v = *(const float4*)(obs + ((size_t)b * SS + t) * EE + c4);
    As[c4][row] = v.x; As[c4 + 1][row] = v.y; As[c4 + 2][row] = v.z; As[c4 + 3][row] = v.w;
  }
  for (int e = tid; e < 128 * 16; e += 256) {
    int row = e >> 4, c4 = (e & 15) * 4;
    float4 v = *(const float4*)(g_Wih + (size_t)(bn * 128 + row) * EE + c4);
    Bs[c4][row] = v.x; Bs[c4 + 1][row] = v.y; Bs[c4 + 2][row] = v.z; Bs[c4 + 3][row] = v.w;
  }
  __syncthreads();
  int tx = tid & 15, ty = tid >> 4;
  float acc[8][8];
#pragma unroll
  for (int i = 0; i < 8; i++)
#pragma unroll
    for (int j = 0; j < 8; j++) acc[i][j] = 0.0f;
#pragma unroll 8
  for (int kk = 0; kk < EE; kk++) {
    float4 av0 = *(const float4*)&As[kk][ty * 8];
    float4 av1 = *(const float4*)&As[kk][ty * 8 + 4];
    float4 bv0 = *(const float4*)&Bs[kk][tx * 8];
    float4 bv1 = *(const float4*)&Bs[kk][tx * 8 + 4];
    float av[8] = {av0.x, av0.y, av0.z, av0.w, av1.x, av1.y, av1.z, av1.w};
    float bv[8] = {bv0.x, bv0.y, bv0.z, bv0.w, bv1.x, bv1.y, bv1.z, bv1.w};
#pragma unroll
    for (int i = 0; i < 8; i++)
#pragma unroll
      for (int j = 0; j < 8; j++) acc[i][j] = fmaf(av[i], bv[j], acc[i][j]);
  }
  float4 bi0 = *(const float4*)(g_bias + bn * 128 + tx * 8);
  float4 bi1 = *(const float4*)(g_bias + bn * 128 + tx * 8 + 4);
#pragma unroll
  for (int i = 0; i < 8; i++) {
    int gr = bm * 128 + ty * 8 + i;
    *(float4*)(g_xg + (size_t)gr * G4 + bn * 128 + tx * 8) =
        make_float4(acc[i][0] + bi0.x, acc[i][1] + bi0.y, acc[i][2] + bi0.z, acc[i][3] + bi0.w);
    *(float4*)(g_xg + (size_t)gr * G4 + bn * 128 + tx * 8 + 4) =
        make_float4(acc[i][4] + bi1.x, acc[i][5] + bi1.y, acc[i][6] + bi1.z, acc[i][7] + bi1.w);
  }
}

__global__ void k_xdot(const float* __restrict__ obs, const float* __restrict__ Wobs) {
  int r = blockIdx.x * 8 + (threadIdx.x >> 5);
  int l = threadIdx.x & 31;
  int t = r >> 5, b = r & 31;
  const float* x = obs + ((size_t)b * SS + t) * EE;
  float acc = fmaf(x[l], Wobs[l], x[l + 32] * Wobs[l + 32]);
#pragma unroll
  for (int off = 16; off; off >>= 1) acc += __shfl_xor_sync(0xffffffffu, acc, off);
  if (l == 0) g_xdot[r] = acc;
}

// ---------------- persistent main: mma.sync fp16x2 GEMM + cell + resample ----------------
// SMEM (dynamic): Bsm [2][128][264] halves (135168 B), Asm [2][128][72] (36864 B)
#define BSM_STRIDE 264
#define BSM_SPLIT  33792     // 128*264
#define ASM_STRIDE 72
#define ASM_SPLIT  9216      // 128*72
#define DYN_BYTES  (2*BSM_SPLIT*2 + 2*ASM_SPLIT*2)   // 172032

extern __shared__ __half dsm16[];

__global__ void __launch_bounds__(NTHR, 1) k_main(
    const float* __restrict__ Wobs, const float* __restrict__ bobs,
    const float* __restrict__ Wout, const float* __restrict__ bout,
    float* __restrict__ out) {
  __shared__ float s_xgb[BB][132];
  __shared__ int   s_perm[128];
  __shared__ float s_pdo[128][2], s_pdu[128][2];
  __shared__ float s_wo[32], s_wu[32];
  __shared__ float s_dobs[PP], s_dout[PP], s_logits[PP], s_pnew[PP];
  __shared__ int   s_idx[PP];

  int bx = blockIdx.x, bn = bx & 7, bm = bx >> 3;
  int tid = threadIdx.x, w = tid >> 5, l = tid & 31;
  int ws = w & 7, nh = w >> 3;        // m-strip / n-half
  int qrow = l >> 2;                  // 0..7
  int qk = (l & 3) << 1;              // k offset (halves)
  int gr = ws * 16 + qrow;

  __half* Bsm = dsm16;
  __half* Asm = dsm16 + 2 * BSM_SPLIT;

  // one-time: B (Whh splits) -> smem, padded rows
  {
    int s = tid >> 8, n = (tid >> 1) & 127, sg = tid & 1;
    const uint4* src = (const uint4*)(g_W16[s] + (size_t)(bn * 128 + n) * HH + sg * 128);
    uint4* dst = (uint4*)(Bsm + s * BSM_SPLIT + n * BSM_STRIDE + sg * 128);
#pragma unroll
    for (int q = 0; q < 16; q++) dst[q] = src[q];
  }
  if (tid < 32) { s_wo[tid] = Wobs[EE + bn * 32 + tid]; s_wu[tid] = Wout[bn * 32 + tid]; }
  float bobs0 = bobs[0], bout0 = bout[0];

  // A-gather thread mapping
  int ga_s = tid & 1, ga_r = (tid >> 1) & 127, ga_sg = tid >> 8;

  for (int t = 0; t < SS; t++) {
    int cur = t & 1, nxt = cur ^ 1;

    if (tid < 128) s_perm[tid] = __ldcg(&g_perm[bm * 128 + tid]);
    {
      const float* srcx = g_xg + (size_t)(t * BB) * G4 + bn * 128;
      for (int e = tid; e < BB * 128; e += NTHR) {
        int b2 = e >> 7, col = e & 127;
        s_xgb[b2][col] = srcx[(size_t)b2 * G4 + col];
      }
    }
    __syncthreads();

    float acc[8][4];
#pragma unroll
    for (int i = 0; i < 8; i++)
#pragma unroll
      for (int j = 0; j < 4; j++) acc[i][j] = 0.0f;

    // prefetch chunk 0 into regs
    int ga_row = s_perm[ga_r];
    uint4 pf[4];
    {
      const uint4* src = (const uint4*)(g_h16[cur][ga_s] + (size_t)ga_row * HH + ga_sg * 32);
#pragma unroll
      for (int q = 0; q < 4; q++) pf[q] = __ldcg(src + q);
    }

    for (int kc = 0; kc < 4; kc++) {
      {
        uint4* dst = (uint4*)(Asm + ga_s * ASM_SPLIT + ga_r * ASM_STRIDE + ga_sg * 32);
#pragma unroll
        for (int q = 0; q < 4; q++) dst[q] = pf[q];
      }
      __syncthreads();
      if (kc < 3) {
        const uint4* src = (const uint4*)(g_h16[cur][ga_s] + (size_t)ga_row * HH + (kc + 1) * 64 + ga_sg * 32);
#pragma unroll
        for (int q = 0; q < 4; q++) pf[q] = __ldcg(src + q);
      }
      const __half* Ab0 = Asm;
      const __half* Ab1 = Asm + ASM_SPLIT;
      const __half* Bp0 = Bsm + kc * 64;
      const __half* Bp1 = Bsm + BSM_SPLIT + kc * 64;
#pragma unroll
      for (int kk = 0; kk < 4; kk++) {
        int klh = (kk << 4) + qk;
        uint32_t a00 = *(const uint32_t*)(Ab0 + gr * ASM_STRIDE + klh);
        uint32_t a01 = *(const uint32_t*)(Ab0 + (gr + 8) * ASM_STRIDE + klh);
        uint32_t a02 = *(const uint32_t*)(Ab0 + gr * ASM_STRIDE + klh + 8);
        uint32_t a03 = *(const uint32_t*)(Ab0 + (gr + 8) * ASM_STRIDE + klh + 8);
        uint32_t a10 = *(const uint32_t*)(Ab1 + gr * ASM_STRIDE + klh);
        uint32_t a11 = *(const uint32_t*)(Ab1 + (gr + 8) * ASM_STRIDE + klh);
        uint32_t a12 = *(const uint32_t*)(Ab1 + gr * ASM_STRIDE + klh + 8);
        uint32_t a13 = *(const uint32_t*)(Ab1 + (gr + 8) * ASM_STRIDE + klh + 8);
#pragma unroll
        for (int nt = 0; nt < 8; nt++) {
          int nrow = nh * 64 + (nt << 3) + qrow;
          uint32_t b0 = *(const uint32_t*)(Bp0 + nrow * BSM_STRIDE + klh);
          uint32_t b1 = *(const uint32_t*)(Bp0 + nrow * BSM_STRIDE + klh + 8);
          mma16816(acc[nt], a00, a01, a02, a03, b0, b1);
          mma16816(acc[nt], a10, a11, a12, a13, b0, b1);
          uint32_t c0 = *(const uint32_t*)(Bp1 + nrow * BSM_STRIDE + klh);
          uint32_t c1 = *(const uint32_t*)(Bp1 + nrow * BSM_STRIDE + klh + 8);
          mma16816(acc[nt], a00, a01, a02, a03, c0, c1);
          mma16816(acc[nt], a10, a11, a12, a13, c0, c1);
        }
      }
      __syncthreads();
    }

    // ---- epilogue: assemble gate quads via lane-pair shuffle, LSTM cell ----
    {
      int par = l & 1;
      int uoff = (l >> 1) & 1;
      int rowloc = ws * 16 + qrow + (par ? 8 : 0);
      int grow = bm * 128 + rowloc;
      int b = rowloc & 31;
      int srow = s_perm[rowloc];
      const float* cold = g_c[cur] + (size_t)srow * HH + bn * 32;
      float* cnew = g_c[nxt] + (size_t)grow * HH + bn * 32;
      __half* h1p = g_h16[nxt][0] + (size_t)grow * HH + bn * 32;
      __half* h2p = g_h16[nxt][1] + (size_t)grow * HH + bn * 32;
      float pobs = 0.f, pout = 0.f;
#pragma unroll
      for (int nt = 0; nt < 8; nt++) {
        float e0 = __shfl_xor_sync(0xffffffffu, acc[nt][0], 1);
        float e1 = __shfl_xor_sync(0xffffffffu, acc[nt][1], 1);
        float e2 = __shfl_xor_sync(0xffffffffu, acc[nt][2], 1);
        float e3 = __shfl_xor_sync(0xffffffffu, acc[nt][3], 1);
        float ig, fg, gg, og;
        if (!par) { ig = acc[nt][0]; fg = acc[nt][1]; gg = e0; og = e1; }
        else      { ig = e2; fg = e3; gg = acc[nt][2]; og = acc[nt][3]; }
        int ul = nh * 16 + (nt << 1) + uoff;          // CTA-local unit 0..31
        float4 xv = *(const float4*)&s_xgb[b][ul << 2];
        ig += xv.x; fg += xv.y; gg += xv.z; og += xv.w;
        float c1 = sigm(fg) * __ldcg(&cold[ul]) + sigm(ig) * tanhf(gg);
        float h1 = sigm(og) * tanhf(c1);
        cnew[ul] = c1;
        __half x1 = __float2half_rn(h1);
        __half x2 = __float2half_rn(h1 - __half2float(x1));
        h1p[ul] = x1; h2p[ul] = x2;
        pobs = fmaf(s_wo[ul], h1, pobs);
        pout = fmaf(s_wu[ul], h1, pout);
      }
      pobs += __shfl_xor_sync(0xffffffffu, pobs, 2);
      pout += __shfl_xor_sync(0xffffffffu, pout, 2);
      if ((l & 2) == 0) { s_pdo[rowloc][nh] = pobs; s_pdu[rowloc][nh] = pout; }
    }
    __syncthreads();
    if (tid < 128) {
      g_pobs[bn][bm * 128 + tid] = s_pdo[tid][0] + s_pdo[tid][1];
      g_pout[bn][bm * 128 + tid] = s_pdu[tid][0] + s_pdu[tid][1];
    }

    grid_sync();

    // ---- resample: CTAs 0..31, one per batch ----
    if (bx < BB) {
      int b = bx;
      if (tid < PP) {
        int r = tid * BB + b;
        float so = 0.0f, du = 0.0f;
#pragma unroll
        for (int nb = 0; nb < 8; nb++) { so += __ldcg(&g_pobs[nb][r]); du += __ldcg(&g_pout[nb][r]); }
        s_dobs[tid] = so; s_dout[tid] = du;
      }
      __syncthreads();

      if (w == 0) {
        float xd = g_xdot[t * BB + b] + bobs0;
        float v0 = s_dobs[l] + xd + __ldcg(&g_p[l * BB + b]);
        float v1 = s_dobs[l + 32] + xd + __ldcg(&g_p[(l + 32) * BB + b]);
        float m = fmaxf(v0, v1);
#pragma unroll
        for (int off = 16; off; off >>= 1) m = fmaxf(m, __shfl_xor_sync(0xffffffffu, m, off));
        float es = expf(v0 - m) + expf(v1 - m);
#pragma unroll
        for (int off = 16; off; off >>= 1) es += __shfl_xor_sync(0xffffffffu, es, off);
        float ls = logf(es);
        float q0 = v0 - m - ls, q1 = v1 - m - ls;
        s_logits[l] = logf(__fadd_rn(__fmul_rn(ALPHA_F, expf(q0)), CMIX_F));
        s_logits[l + 32] = logf(__fadd_rn(__fmul_rn(ALPHA_F, expf(q1)), CMIX_F));
      }
      __syncthreads();

      uint2 sub = g_sub[t];
      for (int i = w; i < PP; i += 16) {
        uint32_t base = (uint32_t)(i * NL + b * PP);
        float g0 = gumbel_from(sub.x, sub.y, base + (uint32_t)l) + s_logits[l];
        float g1 = gumbel_from(sub.x, sub.y, base + (uint32_t)(l + 32)) + s_logits[l + 32];
        float best = g0; int bi = l;
        if (g1 > best) { best = g1; bi = l + 32; }
#pragma unroll
        for (int off = 16; off; off >>= 1) {
          float ov = __shfl_xor_sync(0xffffffffu, best, off);
          int oi = __shfl_xor_sync(0xffffffffu, bi, off);
          if (ov > best || (ov == best && oi < bi)) { best = ov; bi = oi; }
        }
        if (l == 0) s_idx[i] = bi;
      }
      __syncthreads();

      if (w == 0) {
        float lw0 = s_logits[s_idx[l]];
        float lw1 = s_logits[s_idx[l + 32]];
        float m2 = fmaxf(lw0, lw1);
#pragma unroll
        for (int off = 16; off; off >>= 1) m2 = fmaxf(m2, __shfl_xor_sync(0xffffffffu, m2, off));
        float es = expf(lw0 - m2) + expf(lw1 - m2);
#pragma unroll
        for (int off = 16; off; off >>= 1) es += __shfl_xor_sync(0xffffffffu, es, off);
        float ls2 = logf(es);
        float pn0 = lw0 - m2 - ls2, pn1 = lw1 - m2 - ls2;
        s_pnew[l] = pn0; s_pnew[l + 32] = pn1;
        float yl = expf(pn0) * s_dout[s_idx[l]] + expf(pn1) * s_dout[s_idx[l + 32]];
#pragma unroll
        for (int off = 16; off; off >>= 1) yl += __shfl_xor_sync(0xffffffffu, yl, off);
        if (l == 0) out[t * BB + b] = lrelu(yl + bout0);
      }
      __syncthreads();

      if (tid < PP) {
        int i = tid;
        float d = s_dout[s_idx[i]] + bout0;
        out[SS * BB + (size_t)t * NL + i * BB + b] = lrelu(d);
        g_p[i * BB + b] = s_pnew[i];
        g_perm[i * BB + b] = s_idx[i] * BB + b;
      }
    }

    grid_sync();
  }
}

// ---------------- launch ----------------
extern "C" void kernel_launch(void* const* d_in, const int* in_sizes, int n_in,
                              void* d_out, int out_size) {
  const float* obs  = (const float*)d_in[0];
  const float* h0   = (const float*)d_in[1];
  const float* c0   = (const float*)d_in[2];
  const float* Wih  = (const float*)d_in[3];
  const float* bih  = (const float*)d_in[4];
  const float* Whh  = (const float*)d_in[5];
  const float* bhh  = (const float*)d_in[6];
  const float* Wobs = (const float*)d_in[7];
  const float* bobs = (const float*)d_in[8];
  const float* Wout = (const float*)d_in[9];
  const float* bout = (const float*)d_in[10];
  float* out = (float*)d_out;

  cudaFuncSetAttribute(k_main, cudaFuncAttributeMaxDynamicSharedMemorySize, DYN_BYTES);

  k_prep_keys<<<1, 1>>>();
  k_init<<<(NL * HH + 255) / 256, 256>>>(h0, c0);
  k_permW<<<G4, HH>>>(Whh, Wih, bih, bhh);
  k_xg2<<<dim3(8, 32), 256>>>(obs);
  k_xdot<<<SS * BB / 8, 256>>>(obs, Wobs);
  k_main<<<NCTA, NTHR, DYN_BYTES>>>(Wobs, bobs, Wout, bout, out);
  (void)in_sizes; (void)n_in; (void)out_size;
}

// round 11
// speedup vs baseline: 1.4219x; 1.4219x over previous
#include <cuda_runtime.h>
#include <cuda_fp16.h>
#include <cstdint>

#define PP 64
#define HH 256
#define EE 64
#define BB 32
#define SS 128
#define G4 1024
#define NL 2048
#define NCTA 128
#define NTHR 256

#define ALPHA_F 0.1f
#define CMIX_F  0.0140625f
#define TINY_F  1.17549435e-38f

// ---------------- device scratch ----------------
__device__ float g_xg[SS * BB * G4];          // x@Wih^T + biases, gate-permuted cols
__device__ float g_xdot[SS * BB];
__device__ float g_Wih[G4 * EE];              // gate-permuted
__device__ float g_bias[G4];
__device__ __half g_W16[2][G4 * HH];          // Whh gate-permuted fp16 splits, row-major
__device__ __half g_h16[2][2][NL * HH];       // [pingpong][split] h fp16 splits, row-major
__device__ float g_c[2][NL * HH];             // ping-pong c
__device__ int   g_perm[NL];
__device__ float g_p[NL];
__device__ float g_pobs[8][NL];
__device__ float g_pout[8][NL];
__device__ uint2 g_sub[SS];
__device__ unsigned int g_barc, g_barg;

// ---------------- mma.sync helper (baseline PTX, works on compute_103) ----------------
__device__ __forceinline__ void mma16816(float* d, uint32_t a0, uint32_t a1,
                                         uint32_t a2, uint32_t a3,
                                         uint32_t b0, uint32_t b1) {
  asm volatile(
    "mma.sync.aligned.m16n8k16.row.col.f32.f16.f16.f32 "
    "{%0,%1,%2,%3}, {%4,%5,%6,%7}, {%8,%9}, {%0,%1,%2,%3};"
    : "+f"(d[0]), "+f"(d[1]), "+f"(d[2]), "+f"(d[3])
    : "r"(a0), "r"(a1), "r"(a2), "r"(a3), "r"(b0), "r"(b1));
}

// ---------------- grid barrier (128 CTAs, all resident) ----------------
__device__ __forceinline__ void grid_sync() {
  __syncthreads();
  if (threadIdx.x == 0) {
    __threadfence();
    unsigned int gen = *(volatile unsigned int*)&g_barg;
    if (atomicAdd(&g_barc, 1u) == NCTA - 1u) {
      atomicExch(&g_barc, 0u);
      __threadfence();
      atomicAdd(&g_barg, 1u);
    } else {
      while (*(volatile unsigned int*)&g_barg == gen) { __nanosleep(32); }
    }
    __threadfence();
  }
  __syncthreads();
}

// ---------------- threefry / gumbel ----------------
__device__ __forceinline__ void tf2x32(uint32_t k0, uint32_t k1, uint32_t x0, uint32_t x1,
                                       uint32_t& o0, uint32_t& o1) {
  uint32_t ks2 = k0 ^ k1 ^ 0x1BD11BDAu;
  x0 += k0; x1 += k1;
#define TFR(r) { x0 += x1; x1 = (x1 << (r)) | (x1 >> (32 - (r))); x1 ^= x0; }
  TFR(13) TFR(15) TFR(26) TFR(6)   x0 += k1;  x1 += ks2 + 1u;
  TFR(17) TFR(29) TFR(16) TFR(24)  x0 += ks2; x1 += k0  + 2u;
  TFR(13) TFR(15) TFR(26) TFR(6)   x0 += k0;  x1 += k1  + 3u;
  TFR(17) TFR(29) TFR(16) TFR(24)  x0 += k1;  x1 += ks2 + 4u;
  TFR(13) TFR(15) TFR(26) TFR(6)   x0 += ks2; x1 += k0  + 5u;
#undef TFR
  o0 = x0; o1 = x1;
}
__device__ __forceinline__ float gumbel_from(uint32_t k0, uint32_t k1, uint32_t flat) {
  uint32_t o0, o1;
  tf2x32(k0, k1, 0u, flat, o0, o1);
  uint32_t bits = o0 ^ o1;
  float f = __uint_as_float((bits >> 9) | 0x3F800000u) - 1.0f;
  f = fmaxf(f, TINY_F);
  return -logf(-logf(f));
}
__device__ __forceinline__ float sigm(float x) { return 1.0f / (1.0f + expf(-x)); }
__device__ __forceinline__ float lrelu(float x) { return x >= 0.0f ? x : 0.01f * x; }

// ---------------- prologue kernels ----------------
__global__ void k_prep_keys() {
  if (threadIdx.x == 0 && blockIdx.x == 0) {
    uint32_t k0 = 0u, k1 = 42u;
    for (int t = 0; t < SS; t++) {
      uint32_t n0, n1, s0, s1;
      tf2x32(k0, k1, 0u, 0u, n0, n1);
      tf2x32(k0, k1, 0u, 1u, s0, s1);
      g_sub[t] = make_uint2(s0, s1);
      k0 = n0; k1 = n1;
    }
  }
}

__global__ void k_init(const float* __restrict__ h0, const float* __restrict__ c0) {
  int i = blockIdx.x * blockDim.x + threadIdx.x;
  if (i < NL * HH) {
    g_c[0][i] = c0[i];
    float v = h0[i];
    __half a1 = __float2half_rn(v);
    __half a2 = __float2half_rn(v - __half2float(a1));
    g_h16[0][0][i] = a1; g_h16[0][1][i] = a2;
  }
  if (i < NL) { g_p[i] = -4.158883083359672f; g_perm[i] = i; }
}

// gate-permute rows (n = 4u+g <- g*H+u), split Whh to fp16x2, pack Wih + bias
__global__ void k_permW(const float* __restrict__ Whh, const float* __restrict__ Wih,
                        const float* __restrict__ bih, const float* __restrict__ bhh) {
  int n = blockIdx.x;
  int u = n >> 2, g = n & 3;
  int src = g * HH + u;
  int k = threadIdx.x;
  float v = Whh[src * HH + k];
  __half b1 = __float2half_rn(v);
  __half b2 = __float2half_rn(v - __half2float(b1));
  g_W16[0][n * HH + k] = b1;
  g_W16[1][n * HH + k] = b2;
  if (k < EE) g_Wih[n * EE + k] = Wih[src * EE + k];
  if (k == 0) g_bias[n] = bih[src] + bhh[src];
}

// xg = obs-rows @ g_Wih^T + g_bias  (4096x1024, K=64)
__global__ void __launch_bounds__(256, 1) k_xg2(const float* __restrict__ obs) {
  __shared__ float As[EE][132];
  __shared__ float Bs[EE][132];
  int bn = blockIdx.x, bm = blockIdx.y, tid = threadIdx.x;
  for (int e = tid; e < 128 * 16; e += 256) {
    int row = e >> 4, c4 = (e & 15) * 4;
    int gr = bm * 128 + row;
    int t = gr >> 5, b = gr & 31;
    float4 v = *(const float4*)(obs + ((size_t)b * SS + t) * EE + c4);
    As[c4][row] = v.x; As[c4 + 1][row] = v.y; As[c4 + 2][row] = v.z; As[c4 + 3][row] = v.w;
  }
  for (int e = tid; e < 128 * 16; e += 256) {
    int row = e >> 4, c4 = (e & 15) * 4;
    float4 v = *(const float4*)(g_Wih + (size_t)(bn * 128 + row) * EE + c4);
    Bs[c4][row] = v.x; Bs[c4 + 1][row] = v.y; Bs[c4 + 2][row] = v.z; Bs[c4 + 3][row] = v.w;
  }
  __syncthreads();
  int tx = tid & 15, ty = tid >> 4;
  float acc[8][8];
#pragma unroll
  for (int i = 0; i < 8; i++)
#pragma unroll
    for (int j = 0; j < 8; j++) acc[i][j] = 0.0f;
#pragma unroll 8
  for (int kk = 0; kk < EE; kk++) {
    float4 av0 = *(const float4*)&As[kk][ty * 8];
    float4 av1 = *(const float4*)&As[kk][ty * 8 + 4];
    float4 bv0 = *(const float4*)&Bs[kk][tx * 8];
    float4 bv1 = *(const float4*)&Bs[kk][tx * 8 + 4];
    float av[8] = {av0.x, av0.y, av0.z, av0.w, av1.x, av1.y, av1.z, av1.w};
    float bv[8] = {bv0.x, bv0.y, bv0.z, bv0.w, bv1.x, bv1.y, bv1.z, bv1.w};
#pragma unroll
    for (int i = 0; i < 8; i++)
#pragma unroll
      for (int j = 0; j < 8; j++) acc[i][j] = fmaf(av[i], bv[j], acc[i][j]);
  }
  float4 bi0 = *(const float4*)(g_bias + bn * 128 + tx * 8);
  float4 bi1 = *(const float4*)(g_bias + bn * 128 + tx * 8 + 4);
#pragma unroll
  for (int i = 0; i < 8; i++) {
    int gr = bm * 128 + ty * 8 + i;
    *(float4*)(g_xg + (size_t)gr * G4 + bn * 128 + tx * 8) =
        make_float4(acc[i][0] + bi0.x, acc[i][1] + bi0.y, acc[i][2] + bi0.z, acc[i][3] + bi0.w);
    *(float4*)(g_xg + (size_t)gr * G4 + bn * 128 + tx * 8 + 4) =
        make_float4(acc[i][4] + bi1.x, acc[i][5] + bi1.y, acc[i][6] + bi1.z, acc[i][7] + bi1.w);
  }
}

__global__ void k_xdot(const float* __restrict__ obs, const float* __restrict__ Wobs) {
  int r = blockIdx.x * 8 + (threadIdx.x >> 5);
  int l = threadIdx.x & 31;
  int t = r >> 5, b = r & 31;
  const float* x = obs + ((size_t)b * SS + t) * EE;
  float acc = fmaf(x[l], Wobs[l], x[l + 32] * Wobs[l + 32]);
#pragma unroll
  for (int off = 16; off; off >>= 1) acc += __shfl_xor_sync(0xffffffffu, acc, off);
  if (l == 0) g_xdot[r] = acc;
}

// ---------------- persistent main: mma.sync fp16x2 GEMM + cell + resample ----------------
// SMEM (dynamic): Bsm [2][128][264] halves (135168 B), Asm [2][128][72] halves (36864 B).
// The Asm region is reused post-GEMM as fp32 staging: cst[128][36] + hst[128][36].
#define BSM_STRIDE 264
#define BSM_SPLIT  33792     // 128*264
#define ASM_STRIDE 72
#define ASM_SPLIT  9216      // 128*72
#define STG_STRIDE 36        // floats
#define DYN_BYTES  (2*BSM_SPLIT*2 + 2*ASM_SPLIT*2)   // 172032

extern __shared__ __half dsm16[];

__global__ void __launch_bounds__(NTHR, 1) k_main(
    const float* __restrict__ Wobs, const float* __restrict__ bobs,
    const float* __restrict__ Wout, const float* __restrict__ bout,
    float* __restrict__ out) {
  __shared__ float s_xgb[BB][132];
  __shared__ int   s_perm[128];
  __shared__ float s_wo[32], s_wu[32];
  __shared__ float s_dobs[PP], s_dout[PP], s_logits[PP], s_pnew[PP];
  __shared__ int   s_idx[PP];

  int bx = blockIdx.x, bn = bx & 7, bm = bx >> 3;
  int tid = threadIdx.x, w = tid >> 5, l = tid & 31;

  __half* Bsm = dsm16;
  __half* Asm = dsm16 + 2 * BSM_SPLIT;
  float* cst = (float*)Asm;                 // [128][36] fp32, reused post-GEMM
  float* hst = cst + 128 * STG_STRIDE;      // [128][36] fp32

  // one-time: B (Whh splits) -> smem, padded rows
  {
    int s = tid >> 7, n = tid & 127;
    const uint4* src = (const uint4*)(g_W16[s] + (size_t)(bn * 128 + n) * HH);
    uint4* dst = (uint4*)(Bsm + s * BSM_SPLIT + n * BSM_STRIDE);
#pragma unroll
    for (int q = 0; q < 32; q++) dst[q] = src[q];
  }
  if (tid < 32) { s_wo[tid] = Wobs[EE + bn * 32 + tid]; s_wu[tid] = Wout[bn * 32 + tid]; }
  float bobs0 = bobs[0], bout0 = bout[0];

  int gr = (w << 4) + (l >> 2);      // A-frag row (w*16 + l/4)
  int qk = (l & 3) << 1;             // k offset within 16

  for (int t = 0; t < SS; t++) {
    int cur = t & 1, nxt = cur ^ 1;

    if (tid < 128) s_perm[tid] = __ldcg(&g_perm[bm * 128 + tid]);
    {
      const float* srcx = g_xg + (size_t)(t * BB) * G4 + bn * 128;
      for (int e = tid; e < BB * 128; e += NTHR) {
        int b2 = e >> 7, col = e & 127;
        s_xgb[b2][col] = srcx[(size_t)b2 * G4 + col];
      }
    }
    __syncthreads();

    float acc[16][4];
#pragma unroll
    for (int i = 0; i < 16; i++)
#pragma unroll
      for (int j = 0; j < 4; j++) acc[i][j] = 0.0f;

    for (int kc = 0; kc < 4; kc++) {
      // gather A chunk: thread -> (row = tid/2, split = tid&1), 64 halves = 8 uint4
      {
        int r = tid >> 1, s = tid & 1;
        int srow = s_perm[r];
        const uint4* src = (const uint4*)(g_h16[cur][s] + (size_t)srow * HH + kc * 64);
        uint4* dst = (uint4*)(Asm + s * ASM_SPLIT + r * ASM_STRIDE);
#pragma unroll
        for (int q = 0; q < 8; q++) dst[q] = __ldcg(src + q);
      }
      __syncthreads();
#pragma unroll
      for (int ps = 0; ps < 4; ps++) {
        const __half* Ab = Asm + (ps >> 1) * ASM_SPLIT;
        const __half* Bb = Bsm + (ps & 1) * BSM_SPLIT + kc * 64;
#pragma unroll
        for (int kk = 0; kk < 4; kk++) {
          int kl = (kk << 4) + qk;
          uint32_t a0 = *(const uint32_t*)(Ab + gr * ASM_STRIDE + kl);
          uint32_t a1 = *(const uint32_t*)(Ab + (gr + 8) * ASM_STRIDE + kl);
          uint32_t a2 = *(const uint32_t*)(Ab + gr * ASM_STRIDE + kl + 8);
          uint32_t a3 = *(const uint32_t*)(Ab + (gr + 8) * ASM_STRIDE + kl + 8);
#pragma unroll
          for (int nt = 0; nt < 16; nt++) {
            int n = (nt << 3) + (l >> 2);
            uint32_t b0 = *(const uint32_t*)(Bb + n * BSM_STRIDE + kl);
            uint32_t b1 = *(const uint32_t*)(Bb + n * BSM_STRIDE + kl + 8);
            mma16816(acc[nt], a0, a1, a2, a3, b0, b1);
          }
        }
      }
      __syncthreads();
    }

    // ---- stage cold c into smem (coalesced LDG.128), reuse Asm region ----
    for (int q = tid; q < 1024; q += NTHR) {
      int row = q >> 3, part = q & 7;
      int srow = s_perm[row];
      uint4 v = __ldcg((const uint4*)(g_c[cur] + (size_t)srow * HH + bn * 32) + part);
      *(uint4*)(cst + row * STG_STRIDE + part * 4) = v;
    }
    __syncthreads();

    // ---- epilogue: assemble gate quads via lane-pair shuffle, LSTM cell (smem only) ----
    {
      int par = l & 1;                 // 0: rows gr, 1: rows gr+8
      int myhalf = (l >> 1) & 1;       // unit parity within ntile
      int rowloc = (w << 4) + (l >> 2) + (par ? 8 : 0);
      int grow = bm * 128 + rowloc;
      int b = rowloc & 31;
      float* crow = cst + rowloc * STG_STRIDE;
      float* hrow = hst + rowloc * STG_STRIDE;
      float pobs = 0.f, pout = 0.f;
#pragma unroll
      for (int nt = 0; nt < 16; nt++) {
        float e0 = __shfl_xor_sync(0xffffffffu, acc[nt][0], 1);
        float e1 = __shfl_xor_sync(0xffffffffu, acc[nt][1], 1);
        float e2 = __shfl_xor_sync(0xffffffffu, acc[nt][2], 1);
        float e3 = __shfl_xor_sync(0xffffffffu, acc[nt][3], 1);
        float ig, fg, gg, og;
        if (!par) { ig = acc[nt][0]; fg = acc[nt][1]; gg = e0; og = e1; }
        else      { ig = e2; fg = e3; gg = acc[nt][2]; og = acc[nt][3]; }
        int u = (nt << 1) + myhalf;
        float4 xv = *(const float4*)&s_xgb[b][u << 2];
        ig += xv.x; fg += xv.y; gg += xv.z; og += xv.w;
        float c1 = sigm(fg) * crow[u] + sigm(ig) * tanhf(gg);
        float h1 = sigm(og) * tanhf(c1);
        crow[u] = c1;                 // in-place: cold -> new
        hrow[u] = h1;
        pobs = fmaf(s_wo[u], h1, pobs);
        pout = fmaf(s_wu[u], h1, pout);
      }
      pobs += __shfl_xor_sync(0xffffffffu, pobs, 2);
      pout += __shfl_xor_sync(0xffffffffu, pout, 2);
      if ((l & 2) == 0) {
        g_pobs[bn][grow] = pobs;
        g_pout[bn][grow] = pout;
      }
    }
    __syncthreads();

    // ---- coalesced global stores: c (STG.128) and h splits (converted, STG.128) ----
    for (int q = tid; q < 1024; q += NTHR) {
      int row = q >> 3, part = q & 7;
      uint4 v = *(const uint4*)(cst + row * STG_STRIDE + part * 4);
      *((uint4*)(g_c[nxt] + (size_t)(bm * 128 + row) * HH + bn * 32) + part) = v;
    }
    for (int q = tid; q < 512; q += NTHR) {
      int row = q >> 2, part = q & 3;          // 8-half chunk per iteration
      const float* hp = hst + row * STG_STRIDE + part * 8;
      __half s1[8]; __half s2[8];
#pragma unroll
      for (int j = 0; j < 8; j++) {
        float hv = hp[j];
        __half x1 = __float2half_rn(hv);
        s1[j] = x1;
        s2[j] = __float2half_rn(hv - __half2float(x1));
      }
      size_t off = (size_t)(bm * 128 + row) * HH + bn * 32 + part * 8;
      *(uint4*)(g_h16[nxt][0] + off) = *(const uint4*)s1;
      *(uint4*)(g_h16[nxt][1] + off) = *(const uint4*)s2;
    }

    grid_sync();

    // ---- resample: CTAs 0..31, one per batch ----
    if (bx < BB) {
      int b = bx;
      if (tid < PP) {
        int r = tid * BB + b;
        float so = 0.0f, du = 0.0f;
#pragma unroll
        for (int nb = 0; nb < 8; nb++) { so += __ldcg(&g_pobs[nb][r]); du += __ldcg(&g_pout[nb][r]); }
        s_dobs[tid] = so; s_dout[tid] = du;
      }
      __syncthreads();

      if (w == 0) {
        float xd = g_xdot[t * BB + b] + bobs0;
        float v0 = s_dobs[l] + xd + __ldcg(&g_p[l * BB + b]);
        float v1 = s_dobs[l + 32] + xd + __ldcg(&g_p[(l + 32) * BB + b]);
        float m = fmaxf(v0, v1);
#pragma unroll
        for (int off = 16; off; off >>= 1) m = fmaxf(m, __shfl_xor_sync(0xffffffffu, m, off));
        float es = expf(v0 - m) + expf(v1 - m);
#pragma unroll
        for (int off = 16; off; off >>= 1) es += __shfl_xor_sync(0xffffffffu, es, off);
        float ls = logf(es);
        float q0 = v0 - m - ls, q1 = v1 - m - ls;
        s_logits[l] = logf(__fadd_rn(__fmul_rn(ALPHA_F, expf(q0)), CMIX_F));
        s_logits[l + 32] = logf(__fadd_rn(__fmul_rn(ALPHA_F, expf(q1)), CMIX_F));
      }
      __syncthreads();

      uint2 sub = g_sub[t];
      for (int i = w; i < PP; i += 8) {
        uint32_t base = (uint32_t)(i * NL + b * PP);
        float g0 = gumbel_from(sub.x, sub.y, base + (uint32_t)l) + s_logits[l];
        float g1 = gumbel_from(sub.x, sub.y, base + (uint32_t)(l + 32)) + s_logits[l + 32];
        float best = g0; int bi = l;
        if (g1 > best) { best = g1; bi = l + 32; }
#pragma unroll
        for (int off = 16; off; off >>= 1) {
          float ov = __shfl_xor_sync(0xffffffffu, best, off);
          int oi = __shfl_xor_sync(0xffffffffu, bi, off);
          if (ov > best || (ov == best && oi < bi)) { best = ov; bi = oi; }
        }
        if (l == 0) s_idx[i] = bi;
      }
      __syncthreads();

      if (w == 0) {
        float lw0 = s_logits[s_idx[l]];
        float lw1 = s_logits[s_idx[l + 32]];
        float m2 = fmaxf(lw0, lw1);
#pragma unroll
        for (int off = 16; off; off >>= 1) m2 = fmaxf(m2, __shfl_xor_sync(0xffffffffu, m2, off));
        float es = expf(lw0 - m2) + expf(lw1 - m2);
#pragma unroll
        for (int off = 16; off; off >>= 1) es += __shfl_xor_sync(0xffffffffu, es, off);
        float ls2 = logf(es);
        float pn0 = lw0 - m2 - ls2, pn1 = lw1 - m2 - ls2;
        s_pnew[l] = pn0; s_pnew[l + 32] = pn1;
        float yl = expf(pn0) * s_dout[s_idx[l]] + expf(pn1) * s_dout[s_idx[l + 32]];
#pragma unroll
        for (int off = 16; off; off >>= 1) yl += __shfl_xor_sync(0xffffffffu, yl, off);
        if (l == 0) out[t * BB + b] = lrelu(yl + bout0);
      }
      __syncthreads();

      if (tid < PP) {
        int i = tid;
        float d = s_dout[s_idx[i]] + bout0;
        out[SS * BB + (size_t)t * NL + i * BB + b] = lrelu(d);
        g_p[i * BB + b] = s_pnew[i];
        g_perm[i * BB + b] = s_idx[i] * BB + b;
      }
    }

    grid_sync();
  }
}

// ---------------- launch ----------------
extern "C" void kernel_launch(void* const* d_in, const int* in_sizes, int n_in,
                              void* d_out, int out_size) {
  const float* obs  = (const float*)d_in[0];
  const float* h0   = (const float*)d_in[1];
  const float* c0   = (const float*)d_in[2];
  const float* Wih  = (const float*)d_in[3];
  const float* bih  = (const float*)d_in[4];
  const float* Whh  = (const float*)d_in[5];
  const float* bhh  = (const float*)d_in[6];
  const float* Wobs = (const float*)d_in[7];
  const float* bobs = (const float*)d_in[8];
  const float* Wout = (const float*)d_in[9];
  const float* bout = (const float*)d_in[10];
  float* out = (float*)d_out;

  cudaFuncSetAttribute(k_main, cudaFuncAttributeMaxDynamicSharedMemorySize, DYN_BYTES);

  k_prep_keys<<<1, 1>>>();
  k_init<<<(NL * HH + 255) / 256, 256>>>(h0, c0);
  k_permW<<<G4, HH>>>(Whh, Wih, bih, bhh);
  k_xg2<<<dim3(8, 32), 256>>>(obs);
  k_xdot<<<SS * BB / 8, 256>>>(obs, Wobs);
  k_main<<<NCTA, NTHR, DYN_BYTES>>>(Wobs, bobs, Wout, bout, out);
  (void)in_sizes; (void)n_in; (void)out_size;
}

// round 15
// speedup vs baseline: 1.4578x; 1.0252x over previous
#include <cuda_runtime.h>
#include <cuda_fp16.h>
#include <cstdint>

#define PP 64
#define HH 256
#define EE 64
#define BB 32
#define SS 128
#define G4 1024
#define NL 2048
#define NCTA 128
#define NTHR 256

#define ALPHA_F 0.1f
#define CMIX_F  0.0140625f
#define TINY_F  1.17549435e-38f

// ---------------- device scratch ----------------
__device__ float g_xg[SS * BB * G4];          // x@Wih^T + biases, gate-permuted cols
__device__ float g_xdot[SS * BB];
__device__ float g_Wih[G4 * EE];              // gate-permuted
__device__ float g_bias[G4];
__device__ __half g_W16[2][G4 * HH];          // Whh gate-permuted fp16 splits, row-major
__device__ __half g_h16[2][2][NL * HH];       // [pingpong][split] h fp16 splits, row-major
__device__ float g_c[2][NL * HH];             // ping-pong c
__device__ int   g_perm[NL];
__device__ float g_p[NL];
__device__ float g_pobs[8][NL];
__device__ float g_pout[8][NL];
__device__ uint2 g_sub[SS];
__device__ unsigned int g_barc, g_barg;

// ---------------- mma.sync + ldmatrix helpers (baseline PTX) ----------------
__device__ __forceinline__ void mma16816(float* d, uint32_t a0, uint32_t a1,
                                         uint32_t a2, uint32_t a3,
                                         uint32_t b0, uint32_t b1) {
  asm volatile(
    "mma.sync.aligned.m16n8k16.row.col.f32.f16.f16.f32 "
    "{%0,%1,%2,%3}, {%4,%5,%6,%7}, {%8,%9}, {%0,%1,%2,%3};"
    : "+f"(d[0]), "+f"(d[1]), "+f"(d[2]), "+f"(d[3])
    : "r"(a0), "r"(a1), "r"(a2), "r"(a3), "r"(b0), "r"(b1));
}
__device__ __forceinline__ void ldsm_x4(uint32_t& r0, uint32_t& r1, uint32_t& r2,
                                        uint32_t& r3, uint32_t addr) {
  asm volatile("ldmatrix.sync.aligned.m8n8.x4.shared.b16 {%0,%1,%2,%3}, [%4];"
               : "=r"(r0), "=r"(r1), "=r"(r2), "=r"(r3) : "r"(addr));
}
__device__ __forceinline__ uint32_t su32(const void* p) {
  uint32_t a;
  asm("{ .reg .u64 t; cvta.to.shared.u64 t, %1; cvt.u32.u64 %0, t; }" : "=r"(a) : "l"(p));
  return a;
}

// ---------------- grid barrier (128 CTAs, all resident) ----------------
__device__ __forceinline__ void grid_sync() {
  __syncthreads();
  if (threadIdx.x == 0) {
    __threadfence();
    unsigned int gen = *(volatile unsigned int*)&g_barg;
    if (atomicAdd(&g_barc, 1u) == NCTA - 1u) {
      atomicExch(&g_barc, 0u);
      __threadfence();
      atomicAdd(&g_barg, 1u);
    } else {
      while (*(volatile unsigned int*)&g_barg == gen) { __nanosleep(32); }
    }
    __threadfence();
  }
  __syncthreads();
}

// ---------------- threefry / gumbel ----------------
__device__ __forceinline__ void tf2x32(uint32_t k0, uint32_t k1, uint32_t x0, uint32_t x1,
                                       uint32_t& o0, uint32_t& o1) {
  uint32_t ks2 = k0 ^ k1 ^ 0x1BD11BDAu;
  x0 += k0; x1 += k1;
#define TFR(r) { x0 += x1; x1 = (x1 << (r)) | (x1 >> (32 - (r))); x1 ^= x0; }
  TFR(13) TFR(15) TFR(26) TFR(6)   x0 += k1;  x1 += ks2 + 1u;
  TFR(17) TFR(29) TFR(16) TFR(24)  x0 += ks2; x1 += k0  + 2u;
  TFR(13) TFR(15) TFR(26) TFR(6)   x0 += k0;  x1 += k1  + 3u;
  TFR(17) TFR(29) TFR(16) TFR(24)  x0 += k1;  x1 += ks2 + 4u;
  TFR(13) TFR(15) TFR(26) TFR(6)   x0 += ks2; x1 += k0  + 5u;
#undef TFR
  o0 = x0; o1 = x1;
}
__device__ __forceinline__ float gumbel_from(uint32_t k0, uint32_t k1, uint32_t flat) {
  uint32_t o0, o1;
  tf2x32(k0, k1, 0u, flat, o0, o1);
  uint32_t bits = o0 ^ o1;
  float f = __uint_as_float((bits >> 9) | 0x3F800000u) - 1.0f;
  f = fmaxf(f, TINY_F);
  return -logf(-logf(f));
}
__device__ __forceinline__ float sigm(float x) { return 1.0f / (1.0f + expf(-x)); }
__device__ __forceinline__ float lrelu(float x) { return x >= 0.0f ? x : 0.01f * x; }

// ---------------- prologue kernels ----------------
__global__ void k_prep_keys() {
  if (threadIdx.x == 0 && blockIdx.x == 0) {
    uint32_t k0 = 0u, k1 = 42u;
    for (int t = 0; t < SS; t++) {
      uint32_t n0, n1, s0, s1;
      tf2x32(k0, k1, 0u, 0u, n0, n1);
      tf2x32(k0, k1, 0u, 1u, s0, s1);
      g_sub[t] = make_uint2(s0, s1);
      k0 = n0; k1 = n1;
    }
  }
}

__global__ void k_init(const float* __restrict__ h0, const float* __restrict__ c0) {
  int i = blockIdx.x * blockDim.x + threadIdx.x;
  if (i < NL * HH) {
    g_c[0][i] = c0[i];
    float v = h0[i];
    __half a1 = __float2half_rn(v);
    __half a2 = __float2half_rn(v - __half2float(a1));
    g_h16[0][0][i] = a1; g_h16[0][1][i] = a2;
  }
  if (i < NL) { g_p[i] = -4.158883083359672f; g_perm[i] = i; }
}

// gate-permute rows (n = 4u+g <- g*H+u), split Whh to fp16x2, pack Wih + bias
__global__ void k_permW(const float* __restrict__ Whh, const float* __restrict__ Wih,
                        const float* __restrict__ bih, const float* __restrict__ bhh) {
  int n = blockIdx.x;
  int u = n >> 2, g = n & 3;
  int src = g * HH + u;
  int k = threadIdx.x;
  float v = Whh[src * HH + k];
  __half b1 = __float2half_rn(v);
  __half b2 = __float2half_rn(v - __half2float(b1));
  g_W16[0][n * HH + k] = b1;
  g_W16[1][n * HH + k] = b2;
  if (k < EE) g_Wih[n * EE + k] = Wih[src * EE + k];
  if (k == 0) g_bias[n] = bih[src] + bhh[src];
}

// xg = obs-rows @ g_Wih^T + g_bias  (4096x1024, K=64)
__global__ void __launch_bounds__(256, 1) k_xg2(const float* __restrict__ obs) {
  __shared__ float As[EE][132];
  __shared__ float Bs[EE][132];
  int bn = blockIdx.x, bm = blockIdx.y, tid = threadIdx.x;
  for (int e = tid; e < 128 * 16; e += 256) {
    int row = e >> 4, c4 = (e & 15) * 4;
    int gr = bm * 128 + row;
    int t = gr >> 5, b = gr & 31;
    float4 v = *(const float4*)(obs + ((size_t)b * SS + t) * EE + c4);
    As[c4][row] = v.x; As[c4 + 1][row] = v.y; As[c4 + 2][row] = v.z; As[c4 + 3][row] = v.w;
  }
  for (int e = tid; e < 128 * 16; e += 256) {
    int row = e >> 4, c4 = (e & 15) * 4;
    float4 v = *(const float4*)(g_Wih + (size_t)(bn * 128 + row) * EE + c4);
    Bs[c4][row] = v.x; Bs[c4 + 1][row] = v.y; Bs[c4 + 2][row] = v.z; Bs[c4 + 3][row] = v.w;
  }
  __syncthreads();
  int tx = tid & 15, ty = tid >> 4;
  float acc[8][8];
#pragma unroll
  for (int i = 0; i < 8; i++)
#pragma unroll
    for (int j = 0; j < 8; j++) acc[i][j] = 0.0f;
#pragma unroll 8
  for (int kk = 0; kk < EE; kk++) {
    float4 av0 = *(const float4*)&As[kk][ty * 8];
    float4 av1 = *(const float4*)&As[kk][ty * 8 + 4];
    float4 bv0 = *(const float4*)&Bs[kk][tx * 8];
    float4 bv1 = *(const float4*)&Bs[kk][tx * 8 + 4];
    float av[8] = {av0.x, av0.y, av0.z, av0.w, av1.x, av1.y, av1.z, av1.w};
    float bv[8] = {bv0.x, bv0.y, bv0.z, bv0.w, bv1.x, bv1.y, bv1.z, bv1.w};
#pragma unroll
    for (int i = 0; i < 8; i++)
#pragma unroll
      for (int j = 0; j < 8; j++) acc[i][j] = fmaf(av[i], bv[j], acc[i][j]);
  }
  float4 bi0 = *(const float4*)(g_bias + bn * 128 + tx * 8);
  float4 bi1 = *(const float4*)(g_bias + bn * 128 + tx * 8 + 4);
#pragma unroll
  for (int i = 0; i < 8; i++) {
    int gr = bm * 128 + ty * 8 + i;
    *(float4*)(g_xg + (size_t)gr * G4 + bn * 128 + tx * 8) =
        make_float4(acc[i][0] + bi0.x, acc[i][1] + bi0.y, acc[i][2] + bi0.z, acc[i][3] + bi0.w);
    *(float4*)(g_xg + (size_t)gr * G4 + bn * 128 + tx * 8 + 4) =
        make_float4(acc[i][4] + bi1.x, acc[i][5] + bi1.y, acc[i][6] + bi1.z, acc[i][7] + bi1.w);
  }
}

__global__ void k_xdot(const float* __restrict__ obs, const float* __restrict__ Wobs) {
  int r = blockIdx.x * 8 + (threadIdx.x >> 5);
  int l = threadIdx.x & 31;
  int t = r >> 5, b = r & 31;
  const float* x = obs + ((size_t)b * SS + t) * EE;
  float acc = fmaf(x[l], Wobs[l], x[l + 32] * Wobs[l + 32]);
#pragma unroll
  for (int off = 16; off; off >>= 1) acc += __shfl_xor_sync(0xffffffffu, acc, off);
  if (l == 0) g_xdot[r] = acc;
}

// ---------------- persistent main: mma.sync fp16x2 GEMM + cell + resample ----------------
// SMEM (dynamic): Bsm [2][128][264] halves (135168 B), Asm [2][128][72] halves (36864 B).
// The Asm region is reused post-GEMM as fp32 staging: cst[128][36] + hst[128][36].
#define BSM_STRIDE 264
#define BSM_SPLIT  33792     // 128*264
#define ASM_STRIDE 72
#define ASM_SPLIT  9216      // 128*72
#define STG_STRIDE 36        // floats
#define DYN_BYTES  (2*BSM_SPLIT*2 + 2*ASM_SPLIT*2)   // 172032

extern __shared__ __half dsm16[];

__global__ void __launch_bounds__(NTHR, 1) k_main(
    const float* __restrict__ Wobs, const float* __restrict__ bobs,
    const float* __restrict__ Wout, const float* __restrict__ bout,
    float* __restrict__ out) {
  __shared__ float s_xgb[BB][132];
  __shared__ int   s_perm[128];
  __shared__ float s_wo[32], s_wu[32];
  __shared__ float s_dobs[PP], s_dout[PP], s_logits[PP], s_pnew[PP];
  __shared__ int   s_idx[PP];

  int bx = blockIdx.x, bn = bx & 7, bm = bx >> 3;
  int tid = threadIdx.x, w = tid >> 5, l = tid & 31;

  __half* Bsm = dsm16;
  __half* Asm = dsm16 + 2 * BSM_SPLIT;
  float* cst = (float*)Asm;                 // [128][36] fp32, reused post-GEMM
  float* hst = cst + 128 * STG_STRIDE;      // [128][36] fp32

  // one-time: B (Whh splits) -> smem, padded rows
  {
    int s = tid >> 7, n = tid & 127;
    const uint4* src = (const uint4*)(g_W16[s] + (size_t)(bn * 128 + n) * HH);
    uint4* dst = (uint4*)(Bsm + s * BSM_SPLIT + n * BSM_STRIDE);
#pragma unroll
    for (int q = 0; q < 32; q++) dst[q] = src[q];
  }
  if (tid < 32) { s_wo[tid] = Wobs[EE + bn * 32 + tid]; s_wu[tid] = Wout[bn * 32 + tid]; }
  float bobs0 = bobs[0], bout0 = bout[0];

  int ws = w;                        // m-strip 0..7

  // per-lane ldmatrix base addresses (bytes, shared space)
  // A: matrix m = l>>3 -> row_off (m&1)*8, k_off (m>>1)*8 ; row j = l&7
  uint32_t aRow = (uint32_t)(ws * 16 + ((l >> 3) & 1) * 8 + (l & 7));
  uint32_t aBase0 = su32(Asm) + (aRow * ASM_STRIDE + (l >> 4) * 8) * 2;
  uint32_t aBase1 = aBase0 + ASM_SPLIT * 2;
  // B: matrix m = l>>3 -> n_off (m>>1)*8, k_off (m&1)*8 ; row j = l&7
  uint32_t bRow = (uint32_t)((l >> 4) * 8 + (l & 7));
  uint32_t bBase0 = su32(Bsm) + (bRow * BSM_STRIDE + ((l >> 3) & 1) * 8) * 2;
  uint32_t bBase1 = bBase0 + BSM_SPLIT * 2;

  for (int t = 0; t < SS; t++) {
    int cur = t & 1, nxt = cur ^ 1;

    if (tid < 128) s_perm[tid] = __ldcg(&g_perm[bm * 128 + tid]);
    {
      const float* srcx = g_xg + (size_t)(t * BB) * G4 + bn * 128;
      for (int e = tid; e < BB * 128; e += NTHR) {
        int b2 = e >> 7, col = e & 127;
        s_xgb[b2][col] = srcx[(size_t)b2 * G4 + col];
      }
    }
    __syncthreads();

    float acc[16][4];
#pragma unroll
    for (int i = 0; i < 16; i++)
#pragma unroll
      for (int j = 0; j < 4; j++) acc[i][j] = 0.0f;

    for (int kc = 0; kc < 4; kc++) {
      // gather A chunk: thread -> (row = tid/2, split = tid&1), 64 halves = 8 uint4
      {
        int r = tid >> 1, s = tid & 1;
        int srow = s_perm[r];
        const uint4* src = (const uint4*)(g_h16[cur][s] + (size_t)srow * HH + kc * 64);
        uint4* dst = (uint4*)(Asm + s * ASM_SPLIT + r * ASM_STRIDE);
#pragma unroll
        for (int q = 0; q < 8; q++) dst[q] = __ldcg(src + q);
      }
      __syncthreads();
#pragma unroll
      for (int kk = 0; kk < 4; kk++) {
        uint32_t kbA = (uint32_t)(kk * 16) * 2;              // Asm holds current chunk only
        uint32_t kbB = (uint32_t)(kc * 64 + kk * 16) * 2;    // Bsm holds full K
        uint32_t a00, a01, a02, a03, a10, a11, a12, a13;
        ldsm_x4(a00, a01, a02, a03, aBase0 + kbA);
        ldsm_x4(a10, a11, a12, a13, aBase1 + kbA);
#pragma unroll
        for (int nt2 = 0; nt2 < 8; nt2++) {
          uint32_t nb = (uint32_t)(nt2 * 16 * BSM_STRIDE) * 2;
          uint32_t b0, b1, b2, b3, c0, c1, c2, c3;
          ldsm_x4(b0, b1, b2, b3, bBase0 + nb + kbB);
          ldsm_x4(c0, c1, c2, c3, bBase1 + nb + kbB);
          mma16816(acc[2 * nt2],     a00, a01, a02, a03, b0, b1);
          mma16816(acc[2 * nt2],     a00, a01, a02, a03, c0, c1);
          mma16816(acc[2 * nt2],     a10, a11, a12, a13, b0, b1);
          mma16816(acc[2 * nt2],     a10, a11, a12, a13, c0, c1);
          mma16816(acc[2 * nt2 + 1], a00, a01, a02, a03, b2, b3);
          mma16816(acc[2 * nt2 + 1], a00, a01, a02, a03, c2, c3);
          mma16816(acc[2 * nt2 + 1], a10, a11, a12, a13, b2, b3);
          mma16816(acc[2 * nt2 + 1], a10, a11, a12, a13, c2, c3);
        }
      }
      __syncthreads();
    }

    // ---- stage cold c into smem (coalesced LDG.128), reuse Asm region ----
    for (int q = tid; q < 1024; q += NTHR) {
      int row = q >> 3, part = q & 7;
      int srow = s_perm[row];
      uint4 v = __ldcg((const uint4*)(g_c[cur] + (size_t)srow * HH + bn * 32) + part);
      *(uint4*)(cst + row * STG_STRIDE + part * 4) = v;
    }
    __syncthreads();

    // ---- epilogue: assemble gate quads via lane-pair shuffle, LSTM cell (smem only) ----
    {
      int par = l & 1;                 // 0: rows gr, 1: rows gr+8
      int myhalf = (l >> 1) & 1;       // unit parity within ntile
      int rowloc = (w << 4) + (l >> 2) + (par ? 8 : 0);
      int grow = bm * 128 + rowloc;
      int b = rowloc & 31;
      float* crow = cst + rowloc * STG_STRIDE;
      float* hrow = hst + rowloc * STG_STRIDE;
      float pobs = 0.f, pout = 0.f;
#pragma unroll
      for (int nt = 0; nt < 16; nt++) {
        float e0 = __shfl_xor_sync(0xffffffffu, acc[nt][0], 1);
        float e1 = __shfl_xor_sync(0xffffffffu, acc[nt][1], 1);
        float e2 = __shfl_xor_sync(0xffffffffu, acc[nt][2], 1);
        float e3 = __shfl_xor_sync(0xffffffffu, acc[nt][3], 1);
        float ig, fg, gg, og;
        if (!par) { ig = acc[nt][0]; fg = acc[nt][1]; gg = e0; og = e1; }
        else      { ig = e2; fg = e3; gg = acc[nt][2]; og = acc[nt][3]; }
        int u = (nt << 1) + myhalf;
        float4 xv = *(const float4*)&s_xgb[b][u << 2];
        ig += xv.x; fg += xv.y; gg += xv.z; og += xv.w;
        float c1 = sigm(fg) * crow[u] + sigm(ig) * tanhf(gg);
        float h1 = sigm(og) * tanhf(c1);
        crow[u] = c1;                 // in-place: cold -> new
        hrow[u] = h1;
        pobs = fmaf(s_wo[u], h1, pobs);
        pout = fmaf(s_wu[u], h1, pout);
      }
      pobs += __shfl_xor_sync(0xffffffffu, pobs, 2);
      pout += __shfl_xor_sync(0xffffffffu, pout, 2);
      if ((l & 2) == 0) {
        g_pobs[bn][grow] = pobs;
        g_pout[bn][grow] = pout;
      }
    }
    __syncthreads();

    // ---- coalesced global stores: c (STG.128) and h splits (converted, STG.128) ----
    for (int q = tid; q < 1024; q += NTHR) {
      int row = q >> 3, part = q & 7;
      uint4 v = *(const uint4*)(cst + row * STG_STRIDE + part * 4);
      *((uint4*)(g_c[nxt] + (size_t)(bm * 128 + row) * HH + bn * 32) + part) = v;
    }
    for (int q = tid; q < 512; q += NTHR) {
      int row = q >> 2, part = q & 3;          // 8-half chunk per iteration
      const float* hp = hst + row * STG_STRIDE + part * 8;
      __half s1[8]; __half s2[8];
#pragma unroll
      for (int j = 0; j < 8; j++) {
        float hv = hp[j];
        __half x1 = __float2half_rn(hv);
        s1[j] = x1;
        s2[j] = __float2half_rn(hv - __half2float(x1));
      }
      size_t off = (size_t)(bm * 128 + row) * HH + bn * 32 + part * 8;
      *(uint4*)(g_h16[nxt][0] + off) = *(const uint4*)s1;
      *(uint4*)(g_h16[nxt][1] + off) = *(const uint4*)s2;
    }

    grid_sync();

    // ---- resample: CTAs 0..31, one per batch ----
    if (bx < BB) {
      int b = bx;
      if (tid < PP) {
        int r = tid * BB + b;
        float so = 0.0f, du = 0.0f;
#pragma unroll
        for (int nb = 0; nb < 8; nb++) { so += __ldcg(&g_pobs[nb][r]); du += __ldcg(&g_pout[nb][r]); }
        s_dobs[tid] = so; s_dout[tid] = du;
      }
      __syncthreads();

      if (w == 0) {
        float xd = g_xdot[t * BB + b] + bobs0;
        float v0 = s_dobs[l] + xd + __ldcg(&g_p[l * BB + b]);
        float v1 = s_dobs[l + 32] + xd + __ldcg(&g_p[(l + 32) * BB + b]);
        float m = fmaxf(v0, v1);
#pragma unroll
        for (int off = 16; off; off >>= 1) m = fmaxf(m, __shfl_xor_sync(0xffffffffu, m, off));
        float es = expf(v0 - m) + expf(v1 - m);
#pragma unroll
        for (int off = 16; off; off >>= 1) es += __shfl_xor_sync(0xffffffffu, es, off);
        float ls = logf(es);
        float q0 = v0 - m - ls, q1 = v1 - m - ls;
        s_logits[l] = logf(__fadd_rn(__fmul_rn(ALPHA_F, expf(q0)), CMIX_F));
        s_logits[l + 32] = logf(__fadd_rn(__fmul_rn(ALPHA_F, expf(q1)), CMIX_F));
      }
      __syncthreads();

      uint2 sub = g_sub[t];
      for (int i = w; i < PP; i += 8) {
        uint32_t base = (uint32_t)(i * NL + b * PP);
        float g0 = gumbel_from(sub.x, sub.y, base + (uint32_t)l) + s_logits[l];
        float g1 = gumbel_from(sub.x, sub.y, base + (uint32_t)(l + 32)) + s_logits[l + 32];
        float best = g0; int bi = l;
        if (g1 > best) { best = g1; bi = l + 32; }
#pragma unroll
        for (int off = 16; off; off >>= 1) {
          float ov = __shfl_xor_sync(0xffffffffu, best, off);
          int oi = __shfl_xor_sync(0xffffffffu, bi, off);
          if (ov > best || (ov == best && oi < bi)) { best = ov; bi = oi; }
        }
        if (l == 0) s_idx[i] = bi;
      }
      __syncthreads();

      if (w == 0) {
        float lw0 = s_logits[s_idx[l]];
        float lw1 = s_logits[s_idx[l + 32]];
        float m2 = fmaxf(lw0, lw1);
#pragma unroll
        for (int off = 16; off; off >>= 1) m2 = fmaxf(m2, __shfl_xor_sync(0xffffffffu, m2, off));
        float es = expf(lw0 - m2) + expf(lw1 - m2);
#pragma unroll
        for (int off = 16; off; off >>= 1) es += __shfl_xor_sync(0xffffffffu, es, off);
        float ls2 = logf(es);
        float pn0 = lw0 - m2 - ls2, pn1 = lw1 - m2 - ls2;
        s_pnew[l] = pn0; s_pnew[l + 32] = pn1;
        float yl = expf(pn0) * s_dout[s_idx[l]] + expf(pn1) * s_dout[s_idx[l + 32]];
#pragma unroll
        for (int off = 16; off; off >>= 1) yl += __shfl_xor_sync(0xffffffffu, yl, off);
        if (l == 0) out[t * BB + b] = lrelu(yl + bout0);
      }
      __syncthreads();

      if (tid < PP) {
        int i = tid;
        float d = s_dout[s_idx[i]] + bout0;
        out[SS * BB + (size_t)t * NL + i * BB + b] = lrelu(d);
        g_p[i * BB + b] = s_pnew[i];
        g_perm[i * BB + b] = s_idx[i] * BB + b;
      }
    }

    grid_sync();
  }
}

// ---------------- launch ----------------
extern "C" void kernel_launch(void* const* d_in, const int* in_sizes, int n_in,
                              void* d_out, int out_size) {
  const float* obs  = (const float*)d_in[0];
  const float* h0   = (const float*)d_in[1];
  const float* c0   = (const float*)d_in[2];
  const float* Wih  = (const float*)d_in[3];
  const float* bih  = (const float*)d_in[4];
  const float* Whh  = (const float*)d_in[5];
  const float* bhh  = (const float*)d_in[6];
  const float* Wobs = (const float*)d_in[7];
  const float* bobs = (const float*)d_in[8];
  const float* Wout = (const float*)d_in[9];
  const float* bout = (const float*)d_in[10];
  float* out = (float*)d_out;

  cudaFuncSetAttribute(k_main, cudaFuncAttributeMaxDynamicSharedMemorySize, DYN_BYTES);

  k_prep_keys<<<1, 1>>>();
  k_init<<<(NL * HH + 255) / 256, 256>>>(h0, c0);
  k_permW<<<G4, HH>>>(Whh, Wih, bih, bhh);
  k_xg2<<<dim3(8, 32), 256>>>(obs);
  k_xdot<<<SS * BB / 8, 256>>>(obs, Wobs);
  k_main<<<NCTA, NTHR, DYN_BYTES>>>(Wobs, bobs, Wout, bout, out);
  (void)in_sizes; (void)n_in; (void)out_size;
}